// round 1
// baseline (speedup 1.0000x reference)
#include <cuda_runtime.h>
#include <cstdint>

// Scratch for inv_in: [comp][b][i][f], f in 0..255 (f<128: extract00 at channel f; f>=128: trace)
// 2*32*8*256 floats = 512 KB
__device__ float g_inv[2 * 32 * 8 * 256];

// Kernel 1: sparse gather of block column-0 + sub-diagonal.
// One thread per (comp, b, i, c): 2*32*8*128 = 65536 threads.
__global__ void __launch_bounds__(256) gather_kernel(
    const float* __restrict__ Hre,
    const float* __restrict__ Him,
    float* __restrict__ out)
{
    int idx = blockIdx.x * blockDim.x + threadIdx.x;
    int c    = idx & 127;
    int i    = (idx >> 7) & 7;
    int b    = (idx >> 10) & 31;
    int comp = idx >> 15;

    const float* __restrict__ H = comp ? Him : Hre;
    // base of the (b,c) 128x128 matrix
    const float* __restrict__ base = H + ((size_t)((b << 7) + c) << 14);

    const int r0 = i << 4;  // block start row/col

    // Column 0 of the block: H[b,c, r0+k, r0], k = 0..15  (stride 512 B)
    float col[16];
    #pragma unroll
    for (int k = 0; k < 16; k++)
        col[k] = __ldg(base + (size_t)(r0 + k) * 128 + r0);

    // Diagonal of block[1:,1:]: H[b,c, r0+k, r0+k], k = 1..15
    float tr = 0.0f;
    {
        float dg[15];
        #pragma unroll
        for (int k = 1; k < 16; k++)
            dg[k - 1] = __ldg(base + (size_t)(r0 + k) * 128 + (r0 + k));
        #pragma unroll
        for (int k = 0; k < 15; k++)
            tr += dg[k];
    }

    // out shape (2, B, n, C, 16): write slots 1..15 (slot 0 filled by gemm_kernel)
    float* __restrict__ ob =
        out + ((size_t)((((comp << 5) + b) * 8 + i) * 128 + c) << 4);
    #pragma unroll
    for (int l = 1; l < 16; l++)
        ob[l] = col[l];

    // inv_in scratch
    int gi = (((comp << 5) + b) * 8 + i) * 256;
    g_inv[gi + c]       = col[0];  // extract00
    g_inv[gi + 128 + c] = tr;      // trace
}

// Kernel 2: inv = inv_in @ W.T, write to out[..., 0].
// One block per (comp, b): 64 blocks x 128 threads. Thread t = output channel co.
__global__ void __launch_bounds__(128) gemm_kernel(
    const float* __restrict__ Wr,
    const float* __restrict__ Wi,
    float* __restrict__ out)
{
    int blk  = blockIdx.x;
    int comp = blk >> 5;
    int b    = blk & 31;
    const float* __restrict__ W = comp ? Wi : Wr;

    __shared__ float sh[8 * 256];  // inv_in rows for all 8 blocks i

    int t = threadIdx.x;
    int gbase = (((comp << 5) + b) * 8) * 256;
    for (int x = t; x < 8 * 256; x += 128)
        sh[x] = g_inv[gbase + x];
    __syncthreads();

    const int co = t;
    const float* __restrict__ wrow = W + (size_t)co * 256;

    float acc[8];
    #pragma unroll
    for (int i = 0; i < 8; i++) acc[i] = 0.0f;

    #pragma unroll 8
    for (int f = 0; f < 256; f++) {
        float w = __ldg(wrow + f);
        #pragma unroll
        for (int i = 0; i < 8; i++)
            acc[i] += sh[i * 256 + f] * w;  // broadcast read, conflict-free
    }

    #pragma unroll
    for (int i = 0; i < 8; i++) {
        size_t o = ((size_t)((((comp << 5) + b) * 8 + i) * 128 + co) << 4);
        out[o] = acc[i];
    }
}

extern "C" void kernel_launch(void* const* d_in, const int* in_sizes, int n_in,
                              void* d_out, int out_size)
{
    const float* Hre = (const float*)d_in[0];
    const float* Him = (const float*)d_in[1];
    const float* Wr  = (const float*)d_in[2];
    const float* Wi  = (const float*)d_in[3];
    float* out = (float*)d_out;

    // 65536 threads total for gather
    gather_kernel<<<256, 256>>>(Hre, Him, out);
    // 64 blocks for the small GEMM (ordered after gather on same stream)
    gemm_kernel<<<64, 128>>>(Wr, Wi, out);
}